// round 13
// baseline (speedup 1.0000x reference)
#include <cuda_runtime.h>
#include <math.h>

// Problem constants (fixed by the dataset)
#define B_     8
#define V_     25000
#define F_     20000
#define TPB    256
#define TILE   160          // 125 tiles per batch exactly (20000 = 125*160)
#define ROWF   40           // floats per smem row = 160B, 16B-aligned sub-blocks
#define OUTC   1056

typedef unsigned long long u64;

#define FMA2(d, a, bb, c) asm("fma.rn.f32x2 %0, %1, %2, %3;" : "=l"(d) : "l"(a), "l"(bb), "l"(c))
#define STCS2(p, lo, hi)  asm volatile("st.global.cs.v2.u64 [%0], {%1,%2};" :: "l"(p), "l"(lo), "l"(hi) : "memory")
#define BAR0()            asm volatile("bar.sync 0;" ::: "memory")

__device__ __forceinline__ u64 pack2(float lo, float hi) {
    u64 r; asm("mov.b64 %0, {%1,%2};" : "=l"(r) : "f"(lo), "f"(hi)); return r;
}

// Smem row layout (duplicated pairs, float index; 160B row, 16B-aligned sub-blocks):
//   [0..17]  x0..x8 (coor)   [20..25] a0,a1,a2   [28..33] nx,ny,nz
//   [36..37] area            [38..39] emno       (pads zeroed)
//
// Phase structure (per warp, contiguous code; divergent bar.sync 0 joins all 8 warps):
//   w0-w3 : load coor weights            -> bar -> body9  coor cols [0,512)
//   w4    : load 10-slot weights         -> bar -> body10 (coor [512,576) | normal [624,688))
//   w5-w7 : load small weights/consts, then Stage A geometry (96 threads, 1-2 faces each)
//           -> bar -> body3 / const loops
__global__ void __launch_bounds__(TPB, 3)
mc_encode(const float* __restrict__ vertices,
          const int*   __restrict__ faces,
          const float* __restrict__ theta,       const float* __restrict__ phi,
          const float* __restrict__ freq,
          const float* __restrict__ W_angle,     const float* __restrict__ b_angle,
          const float* __restrict__ W_area,      const float* __restrict__ b_area,
          const float* __restrict__ W_normal,    const float* __restrict__ b_normal,
          const float* __restrict__ W_emnoangle, const float* __restrict__ b_emnoangle,
          const float* __restrict__ W_emangle,   const float* __restrict__ b_emangle,
          const float* __restrict__ W_emfreq,    const float* __restrict__ b_emfreq,
          const float* __restrict__ W_coor,      const float* __restrict__ b_coor,
          float* __restrict__ out) {
    __shared__ float sh[TILE * ROWF + 4];   // +4 floats: zero pad past last row
    const int t     = threadIdx.x;
    const int w     = t >> 5;
    const int lane  = t & 31;
    const int b     = blockIdx.y;
    const int fbase = blockIdx.x * TILE;

    const char* X = (const char*)sh;
    const long long ROWB = ROWF * 4;
    float* const obase = out + ((size_t)b * F_ + fbase) * (size_t)OUTC;

    if (w < 4) {                                     // ---- coor warps ----
        const int c0 = 4 * t;
        u64 w01[9], w23[9];
        #pragma unroll
        for (int i = 0; i < 9; i++) {
            float4 wv = *(const float4*)&W_coor[i*576 + c0];
            w01[i] = pack2(wv.x, wv.y);
            w23[i] = pack2(wv.z, wv.w);
        }
        float4 bv = *(const float4*)&b_coor[c0];
        u64 b01 = pack2(bv.x, bv.y), b23 = pack2(bv.z, bv.w);
        if (t < 4) sh[TILE * ROWF + t] = 0.0f;       // zero pad past last row
        BAR0();
        float* op = obase + c0;
        #pragma unroll 2
        for (int ff = 0; ff < TILE; ff++) {
            ulonglong2 q0 = *(const ulonglong2*)(X +  0);
            ulonglong2 q1 = *(const ulonglong2*)(X + 16);
            ulonglong2 q2 = *(const ulonglong2*)(X + 32);
            ulonglong2 q3 = *(const ulonglong2*)(X + 48);
            u64        q8 = *(const u64*)       (X + 64);
            u64 a01 = b01, a23 = b23;
            FMA2(a01, q0.x, w01[0], a01); FMA2(a23, q0.x, w23[0], a23);
            FMA2(a01, q0.y, w01[1], a01); FMA2(a23, q0.y, w23[1], a23);
            FMA2(a01, q1.x, w01[2], a01); FMA2(a23, q1.x, w23[2], a23);
            FMA2(a01, q1.y, w01[3], a01); FMA2(a23, q1.y, w23[3], a23);
            FMA2(a01, q2.x, w01[4], a01); FMA2(a23, q2.x, w23[4], a23);
            FMA2(a01, q2.y, w01[5], a01); FMA2(a23, q2.y, w23[5], a23);
            FMA2(a01, q3.x, w01[6], a01); FMA2(a23, q3.x, w23[6], a23);
            FMA2(a01, q3.y, w01[7], a01); FMA2(a23, q3.y, w23[7], a23);
            FMA2(a01, q8,   w01[8], a01); FMA2(a23, q8,   w23[8], a23);
            STCS2(op, a01, a23);
            op += OUTC; X += ROWB;
        }
    } else if (w == 4) {                             // ---- body10 warp ----
        int o, c0;
        u64 w01[10], w23[10];
        #pragma unroll
        for (int i = 0; i < 10; i++) { w01[i] = 0; w23[i] = 0; }
        if (lane < 16) {                             // coor cols [512,576)
            o = 0; c0 = 512 + 4 * lane;
            #pragma unroll
            for (int i = 0; i < 9; i++) {
                float4 wv = *(const float4*)&W_coor[i*576 + c0];
                w01[i] = pack2(wv.x, wv.y);
                w23[i] = pack2(wv.z, wv.w);
            }
        } else {                                     // normal cols [624,688), slots 4,5,6
            o = 80; c0 = 624 + 4 * (lane - 16);
            int j = c0 - 624;
            #pragma unroll
            for (int i = 0; i < 3; i++) {
                float4 wv = *(const float4*)&W_normal[i*192 + j];
                w01[4+i] = pack2(wv.x, wv.y);
                w23[4+i] = pack2(wv.z, wv.w);
            }
        }
        float4 bv = (lane < 16) ? *(const float4*)&b_coor[c0]
                                : *(const float4*)&b_normal[c0 - 624];
        u64 b01 = pack2(bv.x, bv.y), b23 = pack2(bv.z, bv.w);
        BAR0();
        float* op = obase + c0;
        const char* Xo = X + o;
        #pragma unroll 2
        for (int ff = 0; ff < TILE; ff++) {
            ulonglong2 q0 = *(const ulonglong2*)(Xo +  0);
            ulonglong2 q1 = *(const ulonglong2*)(Xo + 16);
            ulonglong2 q2 = *(const ulonglong2*)(Xo + 32);
            ulonglong2 q3 = *(const ulonglong2*)(Xo + 48);
            ulonglong2 q4 = *(const ulonglong2*)(Xo + 64);
            u64 a01 = b01, a23 = b23;
            FMA2(a01, q0.x, w01[0], a01); FMA2(a23, q0.x, w23[0], a23);
            FMA2(a01, q0.y, w01[1], a01); FMA2(a23, q0.y, w23[1], a23);
            FMA2(a01, q1.x, w01[2], a01); FMA2(a23, q1.x, w23[2], a23);
            FMA2(a01, q1.y, w01[3], a01); FMA2(a23, q1.y, w23[3], a23);
            FMA2(a01, q2.x, w01[4], a01); FMA2(a23, q2.x, w23[4], a23);
            FMA2(a01, q2.y, w01[5], a01); FMA2(a23, q2.y, w23[5], a23);
            FMA2(a01, q3.x, w01[6], a01); FMA2(a23, q3.x, w23[6], a23);
            FMA2(a01, q3.y, w01[7], a01); FMA2(a23, q3.y, w23[7], a23);
            FMA2(a01, q4.x, w01[8], a01); FMA2(a23, q4.x, w23[8], a23);
            FMA2(a01, q4.y, w01[9], a01); FMA2(a23, q4.y, w23[9], a23);
            STCS2(op, a01, a23);
            op += OUTC; Xo += ROWB;
        }
    } else {                                         // ---- w5-w7: prologue + Stage A ----
        const float D2R = 0.017453292519943295f;
        const float th = theta[b] * D2R, ph = phi[b] * D2R;
        const float ix = sinf(ph) * cosf(th);
        const float iy = sinf(ph) * sinf(th);
        const float iz = cosf(ph);

        // --- per-warp prologue (weights / consts into registers) ---
        int o = 80, c0 = 0;
        u64 w01[3], w23[3];
        #pragma unroll
        for (int i = 0; i < 3; i++) { w01[i] = 0; w23[i] = 0; }
        u64 b01 = 0, b23 = 0;
        u64 c01 = 0, c23 = 0, d01 = 0, d23 = 0;      // w7 const payloads
        int c7a = 0, c7b = 0;
        if (w == 5) {                                // normal cols [688,816)
            o = 112; c0 = 688 + 4 * lane;
            int j = c0 - 624;
            #pragma unroll
            for (int i = 0; i < 3; i++) {
                float4 wv = *(const float4*)&W_normal[i*192 + j];
                w01[i] = pack2(wv.x, wv.y);
                w23[i] = pack2(wv.z, wv.w);
            }
            float4 bv = *(const float4*)&b_normal[j];
            b01 = pack2(bv.x, bv.y); b23 = pack2(bv.z, bv.w);
        } else if (w == 6) {                         // mixed 3-slot
            if (lane < 12) {                         // angle cols [576,624)
                o = 80; c0 = 576 + 4 * lane;
                int j = c0 - 576;
                #pragma unroll
                for (int i = 0; i < 3; i++) {
                    float4 wv = *(const float4*)&W_angle[i*48 + j];
                    w01[i] = pack2(wv.x, wv.y);
                    w23[i] = pack2(wv.z, wv.w);
                }
                float4 bv = *(const float4*)&b_angle[j];
                b01 = pack2(bv.x, bv.y); b23 = pack2(bv.z, bv.w);
            } else if (lane < 16) {                  // area cols [816,832): slot0
                o = 144; c0 = 816 + 4 * (lane - 12);
                int j = c0 - 816;
                float4 wv = *(const float4*)&W_area[j];
                w01[0] = pack2(wv.x, wv.y); w23[0] = pack2(wv.z, wv.w);
                float4 bv = *(const float4*)&b_area[j];
                b01 = pack2(bv.x, bv.y); b23 = pack2(bv.z, bv.w);
            } else if (lane < 20) {                  // emnoangle cols [1024,1040): slot1
                o = 144; c0 = 1024 + 4 * (lane - 16);
                int j = c0 - 1024;
                float4 wv = *(const float4*)&W_emnoangle[j];
                w01[1] = pack2(wv.x, wv.y); w23[1] = pack2(wv.z, wv.w);
                float4 bv = *(const float4*)&b_emnoangle[j];
                b01 = pack2(bv.x, bv.y); b23 = pack2(bv.z, bv.w);
            } else {                                 // emangle const cols [832,880)
                o = 80; c0 = 832 + 4 * (lane - 20);
                int j = c0 - 832;
                float4 wa = *(const float4*)&W_emangle[j];
                float4 wb = *(const float4*)&W_emangle[192 + j];
                float4 wc = *(const float4*)&W_emangle[384 + j];
                float4 bb = *(const float4*)&b_emangle[j];
                float4 bv;
                bv.x = ix*wa.x + iy*wb.x + iz*wc.x + bb.x;
                bv.y = ix*wa.y + iy*wb.y + iz*wc.y + bb.y;
                bv.z = ix*wa.z + iy*wb.z + iz*wc.z + bb.z;
                bv.w = ix*wa.w + iy*wb.w + iz*wc.w + bb.w;
                b01 = pack2(bv.x, bv.y); b23 = pack2(bv.z, bv.w);
            }
        } else {                                     // w == 7: pure const payloads
            float4 bv;
            if (lane < 28) {
                c7a = 880 + 4 * lane;
                int j = c7a - 832;
                float4 wa = *(const float4*)&W_emangle[j];
                float4 wb = *(const float4*)&W_emangle[192 + j];
                float4 wc = *(const float4*)&W_emangle[384 + j];
                float4 bb = *(const float4*)&b_emangle[j];
                bv.x = ix*wa.x + iy*wb.x + iz*wc.x + bb.x;
                bv.y = ix*wa.y + iy*wb.y + iz*wc.y + bb.y;
                bv.z = ix*wa.z + iy*wb.z + iz*wc.z + bb.z;
                bv.w = ix*wa.w + iy*wb.w + iz*wc.w + bb.w;
            } else {
                c7a = 1040 + 4 * (lane - 28);
                int j = c7a - 1040;
                float fl = (log10f(freq[b]) + 1.0f) * 0.5f;
                float4 wf = *(const float4*)&W_emfreq[j];
                float4 bf = *(const float4*)&b_emfreq[j];
                bv.x = fl*wf.x + bf.x; bv.y = fl*wf.y + bf.y;
                bv.z = fl*wf.z + bf.z; bv.w = fl*wf.w + bf.w;
            }
            c01 = pack2(bv.x, bv.y); c23 = pack2(bv.z, bv.w);
            c7b = 992 + 4 * lane;                    // second group: emangle [992,1024), lane<8
            {
                int j = ((lane < 8) ? c7b : 992) - 832;
                float4 wa = *(const float4*)&W_emangle[j];
                float4 wb = *(const float4*)&W_emangle[192 + j];
                float4 wc = *(const float4*)&W_emangle[384 + j];
                float4 bb = *(const float4*)&b_emangle[j];
                bv.x = ix*wa.x + iy*wb.x + iz*wc.x + bb.x;
                bv.y = ix*wa.y + iy*wb.y + iz*wc.y + bb.y;
                bv.z = ix*wa.z + iy*wb.z + iz*wc.z + bb.z;
                bv.w = ix*wa.w + iy*wb.w + iz*wc.w + bb.w;
            }
            d01 = pack2(bv.x, bv.y); d23 = pack2(bv.z, bv.w);
        }

        // --- Stage A: 96 threads cover 160 faces (1-2 each) ---
        {
            float inn = 1.0f / fmaxf(sqrtf(ix*ix + iy*iy + iz*iz), 1e-12f);
            const float inc0 = ix * inn, inc1 = iy * inn, inc2 = iz * inn;
            const float* vb = vertices + (size_t)b * V_ * 3;
            for (int f0 = t - 160; f0 < TILE; f0 += 96) {
                const int* fp = faces + ((size_t)b * F_ + fbase + f0) * 3;
                int i0 = fp[0], i1 = fp[1], i2 = fp[2];
                float v0x = vb[3*i0], v0y = vb[3*i0+1], v0z = vb[3*i0+2];
                float v1x = vb[3*i1], v1y = vb[3*i1+1], v1z = vb[3*i1+2];
                float v2x = vb[3*i2], v2y = vb[3*i2+1], v2z = vb[3*i2+2];
                float e0x = v0x - v2x, e0y = v0y - v2y, e0z = v0z - v2z;
                float e1x = v1x - v0x, e1y = v1y - v0y, e1z = v1z - v0z;
                float e2x = v2x - v1x, e2y = v2y - v1y, e2z = v2z - v1z;
                float r0 = 1.0f / fmaxf(sqrtf(e0x*e0x + e0y*e0y + e0z*e0z), 1e-12f);
                float r1 = 1.0f / fmaxf(sqrtf(e1x*e1x + e1y*e1y + e1z*e1z), 1e-12f);
                float r2 = 1.0f / fmaxf(sqrtf(e2x*e2x + e2y*e2y + e2z*e2z), 1e-12f);
                float a0x = e0x*r0, a0y = e0y*r0, a0z = e0z*r0;
                float a1x = e1x*r1, a1y = e1y*r1, a1z = e1z*r1;
                float a2x = e2x*r2, a2y = e2y*r2, a2z = e2z*r2;
                const float LO = -1.0f + 1e-5f, HI = 1.0f - 1e-5f;
                float nd0 = -(a0x*a0z + a1x*a1z + a2x*a2z);
                float nd1 = -(a0y*a0x + a1y*a1x + a2y*a2x);
                float nd2 = -(a0z*a0y + a1z*a1y + a2z*a2y);
                float ang0 = acosf(fminf(fmaxf(nd0, LO), HI));
                float ang1 = acosf(fminf(fmaxf(nd1, LO), HI));
                float ang2 = acosf(fminf(fmaxf(nd2, LO), HI));
                float cx = e0y*e1z - e0z*e1y;
                float cy = e0z*e1x - e0x*e1z;
                float cz = e0x*e1y - e0y*e1x;
                float cn = sqrtf(cx*cx + cy*cy + cz*cz);
                float rc = 1.0f / fmaxf(cn, 1e-12f);
                float nx = cx*rc, ny = cy*rc, nz = cz*rc;
                float area = 0.5f * cn;
                float dd = -(nx*inc0 + ny*inc1 + nz*inc2);
                float emno = acosf(fminf(fmaxf(dd, LO), HI));

                float* R = &sh[f0 * ROWF];
                #define W4(k, a_, b_) *(float4*)&R[k] = make_float4((a_),(a_),(b_),(b_))
                W4(0,  v0x, v0y);  W4(4,  v0z, v1x);
                W4(8,  v1y, v1z);  W4(12, v2x, v2y);
                W4(16, v2z, 0.0f);
                W4(20, ang0, ang1); W4(24, ang2, 0.0f);
                W4(28, nx, ny);     W4(32, nz, 0.0f);
                W4(36, area, emno);
                #undef W4
            }
        }
        BAR0();

        // --- store loops ---
        if (w < 7) {
            float* op = obase + c0;
            const char* Xo = X + o;
            #pragma unroll 4
            for (int ff = 0; ff < TILE; ff++) {
                ulonglong2 q01 = *(const ulonglong2*)(Xo + 0);
                u64        q2  = *(const u64*)       (Xo + 16);
                u64 a01 = b01, a23 = b23;
                FMA2(a01, q01.x, w01[0], a01); FMA2(a23, q01.x, w23[0], a23);
                FMA2(a01, q01.y, w01[1], a01); FMA2(a23, q01.y, w23[1], a23);
                FMA2(a01, q2,    w01[2], a01); FMA2(a23, q2,    w23[2], a23);
                STCS2(op, a01, a23);
                op += OUTC; Xo += ROWB;
            }
        } else {
            const bool two = (lane < 8);
            float* op  = obase + c7a;
            float* op2 = obase + c7b;
            #pragma unroll 4
            for (int ff = 0; ff < TILE; ff++) {
                STCS2(op, c01, c23);
                if (two) STCS2(op2, d01, d23);
                op += OUTC; op2 += OUTC;
            }
        }
    }
}

extern "C" void kernel_launch(void* const* d_in, const int* in_sizes, int n_in,
                              void* d_out, int out_size) {
    const float* vertices    = (const float*)d_in[0];
    const int*   faces       = (const int*)  d_in[1];
    const float* theta       = (const float*)d_in[2];
    const float* phi         = (const float*)d_in[3];
    const float* freq        = (const float*)d_in[4];
    const float* W_angle     = (const float*)d_in[5];
    const float* b_angle     = (const float*)d_in[6];
    const float* W_area      = (const float*)d_in[7];
    const float* b_area      = (const float*)d_in[8];
    const float* W_normal    = (const float*)d_in[9];
    const float* b_normal    = (const float*)d_in[10];
    const float* W_emnoangle = (const float*)d_in[11];
    const float* b_emnoangle = (const float*)d_in[12];
    const float* W_emangle   = (const float*)d_in[13];
    const float* b_emangle   = (const float*)d_in[14];
    const float* W_emfreq    = (const float*)d_in[15];
    const float* b_emfreq    = (const float*)d_in[16];
    const float* W_coor      = (const float*)d_in[17];
    const float* b_coor      = (const float*)d_in[18];

    dim3 grid(F_ / TILE, B_);   // 125 x 8, no partial tiles
    mc_encode<<<grid, TPB>>>(vertices, faces,
                             theta, phi, freq,
                             W_angle, b_angle,
                             W_area, b_area,
                             W_normal, b_normal,
                             W_emnoangle, b_emnoangle,
                             W_emangle, b_emangle,
                             W_emfreq, b_emfreq,
                             W_coor, b_coor,
                             (float*)d_out);
}

// round 15
// speedup vs baseline: 1.0537x; 1.0537x over previous
#include <cuda_runtime.h>
#include <math.h>

// Problem constants (fixed by the dataset)
#define B_     8
#define V_     25000
#define F_     20000
#define TPB    256
#define TILE   160          // 125 tiles per batch exactly (20000 = 125*160)
#define ROWF   44           // floats per smem row = 176B (16B-aligned rows, 4-way STS conflicts)
#define OUTC   1056

typedef unsigned long long u64;

#define FMA2(d, a, bb, c) asm("fma.rn.f32x2 %0, %1, %2, %3;" : "=l"(d) : "l"(a), "l"(bb), "l"(c))
#define STCS2(p, lo, hi)  asm volatile("st.global.cs.v2.u64 [%0], {%1,%2};" :: "l"(p), "l"(lo), "l"(hi) : "memory")
#define BAR224()          asm volatile("bar.sync 1, 224;" ::: "memory")

__device__ __forceinline__ u64 pack2(float lo, float hi) {
    u64 r; asm("mov.b64 %0, {%1,%2};" : "=l"(r) : "f"(lo), "f"(hi)); return r;
}

// Smem row layout (duplicated pairs, float index; 176B row, 16B-aligned sub-blocks):
//   [0..17]  x0..x8 (coor)   [20..25] a0,a1,a2   [28..33] nx,ny,nz
//   [36..37] area            [38..39] emno       [40..43] zero pad
//
// Warp -> body (no intra-warp divergence in the hot loops):
//   w0-w3 : body9  coor cols [0,512)
//   w4    : body10 lane<16: coor [512,576) | lane>=16: normal [624,688)
//   w5    : body3  normal [688,816)
//   w6    : body3  lane<12 angle | lane<16 area | lane<20 emnoangle | else emangle-const [832,880)
//   w7    : const  (no barrier, no smem) lane<28 emangle [880,992) | lane>=28 emfreq [1040,1056)
//             + second store lane<8: emangle [992,1024)
__global__ void __launch_bounds__(TPB, 3)
mc_encode(const float* __restrict__ vertices,
          const int*   __restrict__ faces,
          const float* __restrict__ theta,       const float* __restrict__ phi,
          const float* __restrict__ freq,
          const float* __restrict__ W_angle,     const float* __restrict__ b_angle,
          const float* __restrict__ W_area,      const float* __restrict__ b_area,
          const float* __restrict__ W_normal,    const float* __restrict__ b_normal,
          const float* __restrict__ W_emnoangle, const float* __restrict__ b_emnoangle,
          const float* __restrict__ W_emangle,   const float* __restrict__ b_emangle,
          const float* __restrict__ W_emfreq,    const float* __restrict__ b_emfreq,
          const float* __restrict__ W_coor,      const float* __restrict__ b_coor,
          float* __restrict__ out) {
    __shared__ float sh[TILE * ROWF];
    const int t     = threadIdx.x;
    const int w     = t >> 5;
    const int lane  = t & 31;
    const int b     = blockIdx.y;
    const int fbase = blockIdx.x * TILE;

    // Per-batch incidence vector (raw; normalized where needed)
    const float D2R = 0.017453292519943295f;
    const float th = theta[b] * D2R, ph = phi[b] * D2R;
    const float ix = sinf(ph) * cosf(th);
    const float iy = sinf(ph) * sinf(th);
    const float iz = cosf(ph);

    // ---- Stage A: per-face geometry into shared memory (t < TILE, warps 0-4) ----
    if (t < TILE) {
        float inn = 1.0f / fmaxf(sqrtf(ix*ix + iy*iy + iz*iz), 1e-12f);
        const float inc0 = ix * inn, inc1 = iy * inn, inc2 = iz * inn;
        const int f = fbase + t;
        const int* fp = faces + ((size_t)b * F_ + f) * 3;
        int i0 = fp[0], i1 = fp[1], i2 = fp[2];
        const float* vb = vertices + (size_t)b * V_ * 3;
        float v0x = vb[3*i0], v0y = vb[3*i0+1], v0z = vb[3*i0+2];
        float v1x = vb[3*i1], v1y = vb[3*i1+1], v1z = vb[3*i1+2];
        float v2x = vb[3*i2], v2y = vb[3*i2+1], v2z = vb[3*i2+2];
        float e0x = v0x - v2x, e0y = v0y - v2y, e0z = v0z - v2z;
        float e1x = v1x - v0x, e1y = v1y - v0y, e1z = v1z - v0z;
        float e2x = v2x - v1x, e2y = v2y - v1y, e2z = v2z - v1z;
        float r0 = 1.0f / fmaxf(sqrtf(e0x*e0x + e0y*e0y + e0z*e0z), 1e-12f);
        float r1 = 1.0f / fmaxf(sqrtf(e1x*e1x + e1y*e1y + e1z*e1z), 1e-12f);
        float r2 = 1.0f / fmaxf(sqrtf(e2x*e2x + e2y*e2y + e2z*e2z), 1e-12f);
        float a0x = e0x*r0, a0y = e0y*r0, a0z = e0z*r0;
        float a1x = e1x*r1, a1y = e1y*r1, a1z = e1z*r1;
        float a2x = e2x*r2, a2y = e2y*r2, a2z = e2z*r2;
        const float LO = -1.0f + 1e-5f, HI = 1.0f - 1e-5f;
        float nd0 = -(a0x*a0z + a1x*a1z + a2x*a2z);
        float nd1 = -(a0y*a0x + a1y*a1x + a2y*a2x);
        float nd2 = -(a0z*a0y + a1z*a1y + a2z*a2y);
        float ang0 = acosf(fminf(fmaxf(nd0, LO), HI));
        float ang1 = acosf(fminf(fmaxf(nd1, LO), HI));
        float ang2 = acosf(fminf(fmaxf(nd2, LO), HI));
        float cx = e0y*e1z - e0z*e1y;
        float cy = e0z*e1x - e0x*e1z;
        float cz = e0x*e1y - e0y*e1x;
        float cn = sqrtf(cx*cx + cy*cy + cz*cz);
        float rc = 1.0f / fmaxf(cn, 1e-12f);
        float nx = cx*rc, ny = cy*rc, nz = cz*rc;
        float area = 0.5f * cn;
        float dd = -(nx*inc0 + ny*inc1 + nz*inc2);
        float emno = acosf(fminf(fmaxf(dd, LO), HI));

        float* R = &sh[t * ROWF];
        #define W4(k, a_, b_) *(float4*)&R[k] = make_float4((a_),(a_),(b_),(b_))
        W4(0,  v0x, v0y);  W4(4,  v0z, v1x);
        W4(8,  v1y, v1z);  W4(12, v2x, v2y);
        W4(16, v2z, 0.0f);
        W4(20, ang0, ang1); W4(24, ang2, 0.0f);
        W4(28, nx, ny);     W4(32, nz, 0.0f);
        W4(36, area, emno);
        W4(40, 0.0f, 0.0f);                          // pad: read by area/emno lanes' slot2
        #undef W4
    }
    if (w < 7) BAR224();                             // w7 never syncs (needs no smem)

    // ---- Stage B: warp-uniform packed-FMA loops ----
    const char* X = (const char*)sh;
    const long long ROWB = ROWF * 4;
    float* const obase = out + ((size_t)b * F_ + fbase) * (size_t)OUTC;

    if (w < 4) {                                     // body9: pure coor, cols 4t
        const int c0 = 4 * t;
        u64 w01[9], w23[9];
        #pragma unroll
        for (int i = 0; i < 9; i++) {
            float4 wv = *(const float4*)&W_coor[i*576 + c0];
            w01[i] = pack2(wv.x, wv.y);
            w23[i] = pack2(wv.z, wv.w);
        }
        float4 bv = *(const float4*)&b_coor[c0];
        u64 b01 = pack2(bv.x, bv.y), b23 = pack2(bv.z, bv.w);
        float* op = obase + c0;
        #pragma unroll 2
        for (int ff = 0; ff < TILE; ff++) {
            ulonglong2 q0 = *(const ulonglong2*)(X +  0);
            ulonglong2 q1 = *(const ulonglong2*)(X + 16);
            ulonglong2 q2 = *(const ulonglong2*)(X + 32);
            ulonglong2 q3 = *(const ulonglong2*)(X + 48);
            u64        q8 = *(const u64*)       (X + 64);
            u64 a01 = b01, a23 = b23;
            FMA2(a01, q0.x, w01[0], a01); FMA2(a23, q0.x, w23[0], a23);
            FMA2(a01, q0.y, w01[1], a01); FMA2(a23, q0.y, w23[1], a23);
            FMA2(a01, q1.x, w01[2], a01); FMA2(a23, q1.x, w23[2], a23);
            FMA2(a01, q1.y, w01[3], a01); FMA2(a23, q1.y, w23[3], a23);
            FMA2(a01, q2.x, w01[4], a01); FMA2(a23, q2.x, w23[4], a23);
            FMA2(a01, q2.y, w01[5], a01); FMA2(a23, q2.y, w23[5], a23);
            FMA2(a01, q3.x, w01[6], a01); FMA2(a23, q3.x, w23[6], a23);
            FMA2(a01, q3.y, w01[7], a01); FMA2(a23, q3.y, w23[7], a23);
            FMA2(a01, q8,   w01[8], a01); FMA2(a23, q8,   w23[8], a23);
            STCS2(op, a01, a23);
            op += OUTC; X += ROWB;
        }
    } else if (w == 4) {                             // body10: generic 10-slot
        int o, c0;
        u64 w01[10], w23[10];
        #pragma unroll
        for (int i = 0; i < 10; i++) { w01[i] = 0; w23[i] = 0; }
        if (lane < 16) {                             // coor cols [512,576)
            o = 0; c0 = 512 + 4 * lane;
            #pragma unroll
            for (int i = 0; i < 9; i++) {
                float4 wv = *(const float4*)&W_coor[i*576 + c0];
                w01[i] = pack2(wv.x, wv.y);
                w23[i] = pack2(wv.z, wv.w);
            }
        } else {                                     // normal cols [624,688), slots 4,5,6
            o = 80; c0 = 624 + 4 * (lane - 16);
            int j = c0 - 624;
            #pragma unroll
            for (int i = 0; i < 3; i++) {
                float4 wv = *(const float4*)&W_normal[i*192 + j];
                w01[4+i] = pack2(wv.x, wv.y);
                w23[4+i] = pack2(wv.z, wv.w);
            }
        }
        float4 bv = (lane < 16) ? *(const float4*)&b_coor[c0]
                                : *(const float4*)&b_normal[c0 - 624];
        u64 b01 = pack2(bv.x, bv.y), b23 = pack2(bv.z, bv.w);
        float* op = obase + c0;
        const char* Xo = X + o;
        #pragma unroll 2
        for (int ff = 0; ff < TILE; ff++) {
            ulonglong2 q0 = *(const ulonglong2*)(Xo +  0);
            ulonglong2 q1 = *(const ulonglong2*)(Xo + 16);
            ulonglong2 q2 = *(const ulonglong2*)(Xo + 32);
            ulonglong2 q3 = *(const ulonglong2*)(Xo + 48);
            ulonglong2 q4 = *(const ulonglong2*)(Xo + 64);
            u64 a01 = b01, a23 = b23;
            FMA2(a01, q0.x, w01[0], a01); FMA2(a23, q0.x, w23[0], a23);
            FMA2(a01, q0.y, w01[1], a01); FMA2(a23, q0.y, w23[1], a23);
            FMA2(a01, q1.x, w01[2], a01); FMA2(a23, q1.x, w23[2], a23);
            FMA2(a01, q1.y, w01[3], a01); FMA2(a23, q1.y, w23[3], a23);
            FMA2(a01, q2.x, w01[4], a01); FMA2(a23, q2.x, w23[4], a23);
            FMA2(a01, q2.y, w01[5], a01); FMA2(a23, q2.y, w23[5], a23);
            FMA2(a01, q3.x, w01[6], a01); FMA2(a23, q3.x, w23[6], a23);
            FMA2(a01, q3.y, w01[7], a01); FMA2(a23, q3.y, w23[7], a23);
            FMA2(a01, q4.x, w01[8], a01); FMA2(a23, q4.x, w23[8], a23);
            FMA2(a01, q4.y, w01[9], a01); FMA2(a23, q4.y, w23[9], a23);
            STCS2(op, a01, a23);
            op += OUTC; Xo += ROWB;
        }
    } else if (w < 7) {                              // body3: generic 3-slot
        int o = 80, c0 = 0;
        u64 w01[3], w23[3];
        #pragma unroll
        for (int i = 0; i < 3; i++) { w01[i] = 0; w23[i] = 0; }
        u64 b01, b23;
        if (w == 5) {                                // normal cols [688,816)
            o = 112; c0 = 688 + 4 * lane;
            int j = c0 - 624;
            #pragma unroll
            for (int i = 0; i < 3; i++) {
                float4 wv = *(const float4*)&W_normal[i*192 + j];
                w01[i] = pack2(wv.x, wv.y);
                w23[i] = pack2(wv.z, wv.w);
            }
            float4 bv = *(const float4*)&b_normal[j];
            b01 = pack2(bv.x, bv.y); b23 = pack2(bv.z, bv.w);
        } else if (lane < 12) {                      // angle cols [576,624)
            o = 80; c0 = 576 + 4 * lane;
            int j = c0 - 576;
            #pragma unroll
            for (int i = 0; i < 3; i++) {
                float4 wv = *(const float4*)&W_angle[i*48 + j];
                w01[i] = pack2(wv.x, wv.y);
                w23[i] = pack2(wv.z, wv.w);
            }
            float4 bv = *(const float4*)&b_angle[j];
            b01 = pack2(bv.x, bv.y); b23 = pack2(bv.z, bv.w);
        } else if (lane < 16) {                      // area cols [816,832): slot0
            o = 144; c0 = 816 + 4 * (lane - 12);
            int j = c0 - 816;
            float4 wv = *(const float4*)&W_area[j];
            w01[0] = pack2(wv.x, wv.y); w23[0] = pack2(wv.z, wv.w);
            float4 bv = *(const float4*)&b_area[j];
            b01 = pack2(bv.x, bv.y); b23 = pack2(bv.z, bv.w);
        } else if (lane < 20) {                      // emnoangle cols [1024,1040): slot1
            o = 144; c0 = 1024 + 4 * (lane - 16);
            int j = c0 - 1024;
            float4 wv = *(const float4*)&W_emnoangle[j];
            w01[1] = pack2(wv.x, wv.y); w23[1] = pack2(wv.z, wv.w);
            float4 bv = *(const float4*)&b_emnoangle[j];
            b01 = pack2(bv.x, bv.y); b23 = pack2(bv.z, bv.w);
        } else {                                     // emangle const cols [832,880)
            o = 80; c0 = 832 + 4 * (lane - 20);
            int j = c0 - 832;
            float4 wa = *(const float4*)&W_emangle[j];
            float4 wb = *(const float4*)&W_emangle[192 + j];
            float4 wc = *(const float4*)&W_emangle[384 + j];
            float4 bb = *(const float4*)&b_emangle[j];
            float4 bv;
            bv.x = ix*wa.x + iy*wb.x + iz*wc.x + bb.x;
            bv.y = ix*wa.y + iy*wb.y + iz*wc.y + bb.y;
            bv.z = ix*wa.z + iy*wb.z + iz*wc.z + bb.z;
            bv.w = ix*wa.w + iy*wb.w + iz*wc.w + bb.w;
            b01 = pack2(bv.x, bv.y); b23 = pack2(bv.z, bv.w);
        }
        float* op = obase + c0;
        const char* Xo = X + o;
        #pragma unroll 4
        for (int ff = 0; ff < TILE; ff++) {
            ulonglong2 q01 = *(const ulonglong2*)(Xo + 0);
            u64        q2  = *(const u64*)       (Xo + 16);
            u64 a01 = b01, a23 = b23;
            FMA2(a01, q01.x, w01[0], a01); FMA2(a23, q01.x, w23[0], a23);
            FMA2(a01, q01.y, w01[1], a01); FMA2(a23, q01.y, w23[1], a23);
            FMA2(a01, q2,    w01[2], a01); FMA2(a23, q2,    w23[2], a23);
            STCS2(op, a01, a23);
            op += OUTC; Xo += ROWB;
        }
    } else {                                         // w == 7: pure const, no barrier
        int c0;
        float4 bv;
        if (lane < 28) {
            c0 = 880 + 4 * lane;
            int j = c0 - 832;
            float4 wa = *(const float4*)&W_emangle[j];
            float4 wb = *(const float4*)&W_emangle[192 + j];
            float4 wc = *(const float4*)&W_emangle[384 + j];
            float4 bb = *(const float4*)&b_emangle[j];
            bv.x = ix*wa.x + iy*wb.x + iz*wc.x + bb.x;
            bv.y = ix*wa.y + iy*wb.y + iz*wc.y + bb.y;
            bv.z = ix*wa.z + iy*wb.z + iz*wc.z + bb.z;
            bv.w = ix*wa.w + iy*wb.w + iz*wc.w + bb.w;
        } else {
            c0 = 1040 + 4 * (lane - 28);
            int j = c0 - 1040;
            float fl = (log10f(freq[b]) + 1.0f) * 0.5f;
            float4 wf = *(const float4*)&W_emfreq[j];
            float4 bf = *(const float4*)&b_emfreq[j];
            bv.x = fl*wf.x + bf.x; bv.y = fl*wf.y + bf.y;
            bv.z = fl*wf.z + bf.z; bv.w = fl*wf.w + bf.w;
        }
        u64 c01 = pack2(bv.x, bv.y), c23 = pack2(bv.z, bv.w);

        const bool two = (lane < 8);
        int c1 = 992 + 4 * lane;                     // second group: emangle [992,1024)
        {
            int j = (two ? c1 : 992) - 832;
            float4 wa = *(const float4*)&W_emangle[j];
            float4 wb = *(const float4*)&W_emangle[192 + j];
            float4 wc = *(const float4*)&W_emangle[384 + j];
            float4 bb = *(const float4*)&b_emangle[j];
            bv.x = ix*wa.x + iy*wb.x + iz*wc.x + bb.x;
            bv.y = ix*wa.y + iy*wb.y + iz*wc.y + bb.y;
            bv.z = ix*wa.z + iy*wb.z + iz*wc.z + bb.z;
            bv.w = ix*wa.w + iy*wb.w + iz*wc.w + bb.w;
        }
        u64 d01 = pack2(bv.x, bv.y), d23 = pack2(bv.z, bv.w);
        float* op  = obase + c0;
        float* op2 = obase + c1;
        #pragma unroll 4
        for (int ff = 0; ff < TILE; ff++) {
            STCS2(op, c01, c23);
            if (two) STCS2(op2, d01, d23);
            op += OUTC; op2 += OUTC;
        }
    }
}

extern "C" void kernel_launch(void* const* d_in, const int* in_sizes, int n_in,
                              void* d_out, int out_size) {
    const float* vertices    = (const float*)d_in[0];
    const int*   faces       = (const int*)  d_in[1];
    const float* theta       = (const float*)d_in[2];
    const float* phi         = (const float*)d_in[3];
    const float* freq        = (const float*)d_in[4];
    const float* W_angle     = (const float*)d_in[5];
    const float* b_angle     = (const float*)d_in[6];
    const float* W_area      = (const float*)d_in[7];
    const float* b_area      = (const float*)d_in[8];
    const float* W_normal    = (const float*)d_in[9];
    const float* b_normal    = (const float*)d_in[10];
    const float* W_emnoangle = (const float*)d_in[11];
    const float* b_emnoangle = (const float*)d_in[12];
    const float* W_emangle   = (const float*)d_in[13];
    const float* b_emangle   = (const float*)d_in[14];
    const float* W_emfreq    = (const float*)d_in[15];
    const float* b_emfreq    = (const float*)d_in[16];
    const float* W_coor      = (const float*)d_in[17];
    const float* b_coor      = (const float*)d_in[18];

    dim3 grid(F_ / TILE, B_);   // 125 x 8, no partial tiles
    mc_encode<<<grid, TPB>>>(vertices, faces,
                             theta, phi, freq,
                             W_angle, b_angle,
                             W_area, b_area,
                             W_normal, b_normal,
                             W_emnoangle, b_emnoangle,
                             W_emangle, b_emangle,
                             W_emfreq, b_emfreq,
                             W_coor, b_coor,
                             (float*)d_out);
}